// round 5
// baseline (speedup 1.0000x reference)
#include <cuda_runtime.h>

// KAN_Convolutional_Layer: B=8, CIN=4, H=W=64, OUT=8, K2=9, G=8, Ho=Wo=62
// Fused kernel, 256 blocks x 1024 threads (~86% occupancy):
//   - tile 32x4 outputs; warp = 4 pixels x 8 cg-groups (q = lane>>2)
//   - each thread: 1 pixel, 4 of 32 (c,g) channels; shfl-tree cg reduction
//   - t-planes (stride 204) and weights (stride 76) laid out so every LDS
//     wavefront is bank-conflict-free; single __syncthreads total.

#define B_    8
#define CIN_  4
#define H_    64
#define W_    64
#define OUT_  8
#define K2_   9
#define G_    8
#define HO_   62
#define WO_   62
#define R2_   39.0625f      // R^2 folded into weights

#define TX_    32
#define TY_    4
#define TILW   34
#define TILH   6
#define PLANE  204          // TILH*TILW; 204 % 8 == 4 -> q-groups spread 4 banks
#define WSTR   76           // floats per cg in wsh; 76/4=19 odd -> lines distinct mod 8
#define NTHR   1024

__device__ __forceinline__ unsigned long long pack2(float lo, float hi) {
    unsigned long long r;
    asm("mov.b64 %0, {%1, %2};" : "=l"(r) : "f"(lo), "f"(hi));
    return r;
}
__device__ __forceinline__ void unpack2(unsigned long long v, float& lo, float& hi) {
    asm("mov.b64 {%0, %1}, %2;" : "=f"(lo), "=f"(hi) : "l"(v));
}
__device__ __forceinline__ unsigned long long fma2(unsigned long long a,
                                                   unsigned long long b,
                                                   unsigned long long c) {
    unsigned long long d;
    asm("fma.rn.f32x2 %0, %1, %2, %3;" : "=l"(d) : "l"(a), "l"(b), "l"(c));
    return d;
}
__device__ __forceinline__ unsigned long long add2(unsigned long long a,
                                                   unsigned long long b) {
    unsigned long long d;
    asm("add.rn.f32x2 %0, %1, %2;" : "=l"(d) : "l"(a), "l"(b));
    return d;
}

__global__ void __launch_bounds__(NTHR, 2)
kan_fused_kernel(const float* __restrict__ x,
                 const float* __restrict__ phase_low,
                 const float* __restrict__ phase_high,
                 const float* __restrict__ weight,
                 const float* __restrict__ bias,
                 float* __restrict__ out) {
    __shared__ __align__(16) float tsh[32 * PLANE];   // 26.1 KB
    __shared__ __align__(16) float wsh[32 * WSTR];    //  9.7 KB
    __shared__ float bsh[OUT_];

    const int b   = blockIdx.z;
    const int x0  = blockIdx.x * TX_;   // 0 or 32
    const int y0  = blockIdx.y * TY_;   // 0..60
    const int tid = threadIdx.x;

    // ---- weight reorder with R^2: wsh[cg*WSTR + f*8 + o], cg = c*8+g
#pragma unroll
    for (int it = 0; it < 3; it++) {
        int i = tid + it * NTHR;
        if (i < 32 * K2_ * OUT_) {
            int o  = i & 7;
            int f  = (i >> 3) % K2_;
            int cg = i / (OUT_ * K2_);
            int g  = cg & 7;
            int c  = cg >> 3;
            wsh[cg * WSTR + f * OUT_ + o] =
                weight[((o * CIN_ + c) * K2_ + f) * G_ + g] * R2_;
        }
    }
    if (tid < OUT_) {
        float s = 0.0f;
#pragma unroll
        for (int c = 0; c < CIN_; c++) s += bias[tid * CIN_ + c];
        bsh[tid] = s;
    }

    // ---- spline t-fill: one position per thread (816 < 1024)
    if (tid < CIN_ * PLANE) {
        int c   = tid / PLANE;
        int pos = tid - c * PLANE;
        int row = pos / TILW;
        int col = pos - row * TILW;
        int gy = y0 + row, gx = x0 + col;
        float xv = 0.0f;
        if (gy < H_ && gx < W_)
            xv = __ldg(&x[((b * CIN_ + c) * H_ + gy) * W_ + gx]);
        float pl0 = __ldg(&phase_low[0]);     // broadcast arrays: pl_g = pl0 + g/5
        float ph0 = __ldg(&phase_high[0]);
#pragma unroll
        for (int g = 0; g < G_; g++) {
            float a = fmaxf(xv - (pl0 + 0.2f * g), 0.0f);
            float d = fmaxf((ph0 + 0.2f * g) - xv, 0.0f);
            float m = a * d;
            tsh[(c * G_ + g) * PLANE + pos] = m * m;   // R^2 lives in weights
        }
    }
    __syncthreads();

    // ---- conv: lane -> (q, pixel);  q handles cg = q + 8*i, i = 0..3
    const int w   = tid >> 5;
    const int l   = tid & 31;
    const int q   = l >> 2;            // 0..7
    const int sub = l & 3;
    const int pix = w * 4 + sub;       // 0..127
    const int tx  = pix & 31;
    const int ty  = pix >> 5;          // 0..3

    unsigned long long acc0 = 0, acc1 = 0, acc2 = 0, acc3 = 0;
    const float* pb_base = tsh + q * PLANE + ty * TILW + tx;
    const float* wp_base = wsh + q * WSTR;

#pragma unroll
    for (int i = 0; i < 4; i++) {
        const float* pb = pb_base + i * (8 * PLANE);
        const float* wp = wp_base + i * (8 * WSTR);

        float tv[K2_];
#pragma unroll
        for (int fi = 0; fi < 3; fi++)
#pragma unroll
            for (int fj = 0; fj < 3; fj++)
                tv[fi * 3 + fj] = pb[fi * TILW + fj];

#pragma unroll
        for (int f = 0; f < K2_; f++) {
            unsigned long long tvp = pack2(tv[f], tv[f]);
            const ulonglong2* w2 = reinterpret_cast<const ulonglong2*>(wp + f * OUT_);
            ulonglong2 wa = w2[0];   // o0..o3
            ulonglong2 wb = w2[1];   // o4..o7
            acc0 = fma2(tvp, wa.x, acc0);
            acc1 = fma2(tvp, wa.y, acc1);
            acc2 = fma2(tvp, wb.x, acc2);
            acc3 = fma2(tvp, wb.y, acc3);
        }
    }

    // ---- reduce across the 8 q-groups (lanes xor 4, 8, 16)
#pragma unroll
    for (int m = 4; m <= 16; m <<= 1) {
        acc0 = add2(acc0, __shfl_xor_sync(0xffffffffu, acc0, m));
        acc1 = add2(acc1, __shfl_xor_sync(0xffffffffu, acc1, m));
        acc2 = add2(acc2, __shfl_xor_sync(0xffffffffu, acc2, m));
        acc3 = add2(acc3, __shfl_xor_sync(0xffffffffu, acc3, m));
    }

    if (q == 0) {
        const int ox = x0 + tx;
        const int oy = y0 + ty;
        if (ox < WO_ && oy < HO_) {
            float v[OUT_];
            unpack2(acc0, v[0], v[1]);
            unpack2(acc1, v[2], v[3]);
            unpack2(acc2, v[4], v[5]);
            unpack2(acc3, v[6], v[7]);
#pragma unroll
            for (int o = 0; o < OUT_; o++)
                out[((b * OUT_ + o) * HO_ + oy) * WO_ + ox] = v[o] + bsh[o];
        }
    }
}

// ---------------------------------------------------------------------------
extern "C" void kernel_launch(void* const* d_in, const int* in_sizes, int n_in,
                              void* d_out, int out_size) {
    const float* x          = (const float*)d_in[0];
    const float* phase_low  = (const float*)d_in[1];
    const float* phase_high = (const float*)d_in[2];
    const float* weight     = (const float*)d_in[3];
    const float* bias       = (const float*)d_in[4];
    float* out = (float*)d_out;

    dim3 grid((WO_ + TX_ - 1) / TX_,     // 2
              (HO_ + TY_ - 1) / TY_,     // 16
              B_);                       // 8  -> 256 blocks x 1024 threads
    kan_fused_kernel<<<grid, NTHR>>>(x, phase_low, phase_high, weight, bias, out);
}

// round 6
// speedup vs baseline: 1.1775x; 1.1775x over previous
#include <cuda_runtime.h>

// KAN_Convolutional_Layer: B=8, CIN=4, H=W=64, OUT=8, K2=9, G=8, Ho=Wo=62
// Strip-mined fused kernel, 128 blocks x 512 threads:
//   - block tile 32x8 outputs; thread = 4-px horizontal strip x 8 outputs,
//     over 4 of 32 (c,g) channels (8-way cg split, q = lane>>2)
//   - weights duplicated (w,w) in smem -> fma2(px_pair, w_dup, acc) does 2 px/op
//   - t-planes staged over c-pairs (16 planes / 23.5KB) + dup weights (18.4KB)
//   - plane stride 368 & weight stride 144 (both ==16 mod 32): conflict-free LDS
//   - butterfly half-exchange reduction: every lane ends with one output channel

#define B_    8
#define CIN_  4
#define H_    64
#define W_    64
#define OUT_  8
#define K2_   9
#define G_    8
#define HO_   62
#define WO_   62
#define R2_   39.0625f     // R^2 folded into weights

#define TILW  36           // 32 px + 2 halo + 2 align pad (keeps LDS.128 aligned)
#define TILH  10           // 8 rows + 2 halo
#define NPOS  (TILH*TILW)  // 360
#define PSTR  368          // plane stride (words); 368 % 32 == 16
#define WCG   144          // floats per cg in wdup (9*16); 144 % 32 == 16
#define NTHR  512

typedef unsigned long long u64;

__device__ __forceinline__ u64 pack2(float lo, float hi) {
    u64 r;
    asm("mov.b64 %0, {%1, %2};" : "=l"(r) : "f"(lo), "f"(hi));
    return r;
}
__device__ __forceinline__ void unpack2(u64 v, float& lo, float& hi) {
    asm("mov.b64 {%0, %1}, %2;" : "=f"(lo), "=f"(hi) : "l"(v));
}
__device__ __forceinline__ u64 fma2(u64 a, u64 b, u64 c) {
    u64 d;
    asm("fma.rn.f32x2 %0, %1, %2, %3;" : "=l"(d) : "l"(a), "l"(b), "l"(c));
    return d;
}
__device__ __forceinline__ u64 add2(u64 a, u64 b) {
    u64 d;
    asm("add.rn.f32x2 %0, %1, %2;" : "=l"(d) : "l"(a), "l"(b));
    return d;
}

__global__ void __launch_bounds__(NTHR, 1)
kan_fused_kernel(const float* __restrict__ x,
                 const float* __restrict__ phase_low,
                 const float* __restrict__ phase_high,
                 const float* __restrict__ weight,
                 const float* __restrict__ bias,
                 float* __restrict__ out) {
    __shared__ __align__(16) float tsh[16 * PSTR];   // 23.5 KB (one c-pair stage)
    __shared__ __align__(16) float wsh[32 * WCG];    // 18.4 KB, dup'd weights
    __shared__ float bsh[OUT_];

    const int b   = blockIdx.z;
    const int x0  = blockIdx.x * 32;
    const int y0  = blockIdx.y * 8;
    const int tid = threadIdx.x;

    // ---- duplicated weights: wsh[cg*WCG + f*16 + o*2 + {0,1}] = w*R^2
#pragma unroll
    for (int it = 0; it < 5; it++) {
        int i = tid + it * NTHR;
        if (i < 32 * K2_ * OUT_) {
            int o  = i & 7;
            int f  = (i >> 3) % K2_;
            int cg = i / (K2_ * OUT_);
            int g  = cg & 7;
            int c  = cg >> 3;
            float wv = weight[((o * CIN_ + c) * K2_ + f) * G_ + g] * R2_;
            int base = cg * WCG + f * 16 + o * 2;
            wsh[base]     = wv;
            wsh[base + 1] = wv;
        }
    }
    if (tid < OUT_) {
        float s = 0.0f;
#pragma unroll
        for (int c = 0; c < CIN_; c++) s += bias[tid * CIN_ + c];
        bsh[tid] = s;
    }

    float pl[G_], ph[G_];
#pragma unroll
    for (int g = 0; g < G_; g++) {
        pl[g] = __ldg(&phase_low[g]);   // broadcast over (o,c,f) by construction
        ph[g] = __ldg(&phase_high[g]);
    }

    // ---- lane decomposition: warp w, lane l; q = cg group, sub = strip in warp
    const int w   = tid >> 5;
    const int l   = tid & 31;
    const int q   = l >> 2;             // 0..7
    const int sub = l & 3;
    const int sy  = w >> 1;             // strip row 0..7
    const int sx  = (w & 1) * 4 + sub;  // strip col 0..7 (strip = 4 px wide)

    u64 acc[OUT_][2];
#pragma unroll
    for (int o = 0; o < OUT_; o++) { acc[o][0] = 0; acc[o][1] = 0; }

#pragma unroll
    for (int s = 0; s < 2; s++) {       // c-pair stages {0,1}, {2,3}
        __syncthreads();                // prior stage reads done
        // -- spline fill: 2 c-planes x 8 g, 360 positions each
#pragma unroll
        for (int it = 0; it < 2; it++) {
            int i = tid + it * NTHR;
            if (i < 2 * NPOS) {
                int cl  = i >= NPOS;
                int pos = i - cl * NPOS;
                int row = pos / TILW;
                int col = pos - row * TILW;
                int gy = y0 + row, gx = x0 + col;
                float xv = 0.0f;
                if (gy < H_ && gx < W_)
                    xv = __ldg(&x[((b * CIN_ + 2 * s + cl) * H_ + gy) * W_ + gx]);
#pragma unroll
                for (int g = 0; g < G_; g++) {
                    float a = fmaxf(xv - pl[g], 0.0f);
                    float d = fmaxf(ph[g] - xv, 0.0f);
                    float m = a * d;
                    tsh[(cl * G_ + g) * PSTR + pos] = m * m;   // R^2 in weights
                }
            }
        }
        __syncthreads();

        // -- conv: q handles planes q and q+8 of this stage
#pragma unroll
        for (int i = 0; i < 2; i++) {
            const int p = q + 8 * i;                     // plane 0..15
            const float* pb = tsh + p * PSTR + sy * TILW + 4 * sx;  // 16B aligned
            const float* wp = wsh + (s * 16 + p) * WCG;

            // tv: 3 rows x 6 cols; pairs per (row, fj)
            u64 pr[3][3][2];
#pragma unroll
            for (int r = 0; r < 3; r++) {
                float4 v4 = *reinterpret_cast<const float4*>(pb + r * TILW);
                float2 v2 = *reinterpret_cast<const float2*>(pb + r * TILW + 4);
                u64 p01 = pack2(v4.x, v4.y);
                u64 p23 = pack2(v4.z, v4.w);
                u64 p45 = pack2(v2.x, v2.y);
                pr[r][0][0] = p01;               pr[r][0][1] = p23;
                pr[r][1][0] = pack2(v4.y, v4.z); pr[r][1][1] = pack2(v4.w, v2.x);
                pr[r][2][0] = p23;               pr[r][2][1] = p45;
            }

#pragma unroll
            for (int fi = 0; fi < 3; fi++) {
#pragma unroll
                for (int fj = 0; fj < 3; fj++) {
                    const ulonglong2* wv =
                        reinterpret_cast<const ulonglong2*>(wp + (fi * 3 + fj) * 16);
                    ulonglong2 w01 = wv[0];   // dup'd o0, o1
                    ulonglong2 w23 = wv[1];
                    ulonglong2 w45 = wv[2];
                    ulonglong2 w67 = wv[3];
                    u64 ta = pr[fi][fj][0];   // (px0, px1)
                    u64 tb = pr[fi][fj][1];   // (px2, px3)
                    acc[0][0] = fma2(ta, w01.x, acc[0][0]);
                    acc[0][1] = fma2(tb, w01.x, acc[0][1]);
                    acc[1][0] = fma2(ta, w01.y, acc[1][0]);
                    acc[1][1] = fma2(tb, w01.y, acc[1][1]);
                    acc[2][0] = fma2(ta, w23.x, acc[2][0]);
                    acc[2][1] = fma2(tb, w23.x, acc[2][1]);
                    acc[3][0] = fma2(ta, w23.y, acc[3][0]);
                    acc[3][1] = fma2(tb, w23.y, acc[3][1]);
                    acc[4][0] = fma2(ta, w45.x, acc[4][0]);
                    acc[4][1] = fma2(tb, w45.x, acc[4][1]);
                    acc[5][0] = fma2(ta, w45.y, acc[5][0]);
                    acc[5][1] = fma2(tb, w45.y, acc[5][1]);
                    acc[6][0] = fma2(ta, w67.x, acc[6][0]);
                    acc[6][1] = fma2(tb, w67.x, acc[6][1]);
                    acc[7][0] = fma2(ta, w67.y, acc[7][0]);
                    acc[7][1] = fma2(tb, w67.y, acc[7][1]);
                }
            }
        }
    }

    // ---- butterfly half-exchange reduction over the 8 q-groups
    // A[o*2 + pair]; levels on q bits 0,1,2 <-> lane masks 4,8,16
    u64 A[16];
#pragma unroll
    for (int o = 0; o < OUT_; o++) { A[o * 2] = acc[o][0]; A[o * 2 + 1] = acc[o][1]; }

#pragma unroll
    for (int lvl = 0; lvl < 3; lvl++) {
        const int mask = 4 << lvl;
        const int half = 8 >> lvl;
        const bool bit = (q >> lvl) & 1;
#pragma unroll
        for (int j = 0; j < 8; j++) {
            if (j < half) {
                u64 lo = A[j], hi = A[half + j];
                u64 sent = bit ? lo : hi;
                u64 rec  = __shfl_xor_sync(0xffffffffu, sent, mask);
                A[j] = add2(bit ? hi : lo, rec);
            }
        }
    }
    // lane q now holds o = bitrev3(q): A[0]=(px0,px1), A[1]=(px2,px3)
    const int o = ((q & 1) << 2) | (q & 2) | (q >> 2);

    float v0, v1, v2, v3;
    unpack2(A[0], v0, v1);
    unpack2(A[1], v2, v3);
    const float bo = bsh[o];
    const int oy  = y0 + sy;
    const int ox0 = x0 + 4 * sx;
    if (oy < HO_) {
        float* op = out + ((b * OUT_ + o) * HO_ + oy) * WO_ + ox0;
        if (ox0 + 0 < WO_) op[0] = v0 + bo;
        if (ox0 + 1 < WO_) op[1] = v1 + bo;
        if (ox0 + 2 < WO_) op[2] = v2 + bo;
        if (ox0 + 3 < WO_) op[3] = v3 + bo;
    }
}

// ---------------------------------------------------------------------------
extern "C" void kernel_launch(void* const* d_in, const int* in_sizes, int n_in,
                              void* d_out, int out_size) {
    const float* x          = (const float*)d_in[0];
    const float* phase_low  = (const float*)d_in[1];
    const float* phase_high = (const float*)d_in[2];
    const float* weight     = (const float*)d_in[3];
    const float* bias       = (const float*)d_in[4];
    float* out = (float*)d_out;

    dim3 grid(2, 8, B_);                 // 128 blocks x 512 threads
    kan_fused_kernel<<<grid, NTHR>>>(x, phase_low, phase_high, weight, bias, out);
}